// round 13
// baseline (speedup 1.0000x reference)
#include <cuda_runtime.h>
#include <cuda_fp16.h>
#include <math.h>

#define B_TOK 4096
#define D_DIM 9216
#define E_EXP 8
#define H_DIM 128
#define O_DIM 10
#define SPLITS 6
#define KCH (D_DIM / SPLITS)   // 1536
#define GTOK 8

// ---------------- scratch (static device globals) ----------------------------
__device__ unsigned g_hp[(size_t)B_TOK * D_DIM];      // h packed (hi, lo*2048)
__device__ float    g_scale[B_TOK];
__device__ int      g_bucket[E_EXP * B_TOK];
__device__ int      g_cnt[E_EXP];
__device__ float    g_part[SPLITS][B_TOK][H_DIM];
__device__ unsigned g_w1h[(size_t)E_EXP * 4608 * 128]; // w1 fp16 k-pairs

__global__ void reset_kernel() {
    if (threadIdx.x < E_EXP) g_cnt[threadIdx.x] = 0;
}

// ---------------- helpers ----------------------------------------------------
__device__ __forceinline__ void mma_f16(float c[4],
                                        unsigned a0, unsigned a1,
                                        unsigned a2, unsigned a3,
                                        unsigned b0, unsigned b1) {
    asm("mma.sync.aligned.m16n8k16.row.col.f32.f16.f16.f32 "
        "{%0,%1,%2,%3},{%4,%5,%6,%7},{%8,%9},{%0,%1,%2,%3};"
        : "+f"(c[0]), "+f"(c[1]), "+f"(c[2]), "+f"(c[3])
        : "r"(a0), "r"(a1), "r"(a2), "r"(a3), "r"(b0), "r"(b1));
}
__device__ __forceinline__ unsigned h2u(__half2 h) { return *reinterpret_cast<unsigned*>(&h); }
__device__ __forceinline__ __half2 u2h(unsigned u) { return *reinterpret_cast<__half2*>(&u); }
__device__ __forceinline__ float unpackh(unsigned u) {
    return __half2float(__ushort_as_half((unsigned short)(u & 0xffff)))
         + __half2float(__ushort_as_half((unsigned short)(u >> 16))) * 4.8828125e-4f;
}
__device__ __forceinline__ unsigned packh(float v) {
    __half hi = __float2half_rn(v);
    __half lo = __float2half_rn((v - __half2float(hi)) * 2048.f);
    return ((unsigned)__half_as_ushort(lo) << 16) | (unsigned)__half_as_ushort(hi);
}

// ---------------- w1 -> fp16 k-pair pack -------------------------------------
__global__ __launch_bounds__(256)
void w1pack_kernel(const float* __restrict__ w1) {
    size_t idx = (size_t)blockIdx.x * 256 + threadIdx.x;
    int n   = (int)(idx & 127);
    int row = (int)(idx >> 7);
    int e   = row / 4608;
    int kp  = row - e * 4608;
    const float* we = w1 + (size_t)e * D_DIM * H_DIM;
    float w0 = we[(size_t)(2 * kp) * 128 + n];
    float w1v = we[(size_t)(2 * kp + 1) * 128 + n];
    g_w1h[idx] = h2u(__floats2half2_rn(w0, w1v));
}

// ---------------- fused conv1 -> conv2(fp16 3-term mma) -> maxpool -----------
#define CONV_THREADS 576
#define NKS 18
#define OFF_IN   0
#define OFF_C1W  784
#define OFF_C1B  1072
#define OFF_C2B  1104
#define OFF_COFF 1168
#define OFF_C1   1456
#define OFF_BF   (OFF_C1 + 21632)
#define BF_U2    (3 * 8 * NKS * 32)
#define CONV_SMEM_FLOATS (OFF_BF + BF_U2 * 2)

__global__ __launch_bounds__(CONV_THREADS, 1)
void conv_kernel(const float* __restrict__ x,
                 const float* __restrict__ c1w, const float* __restrict__ c1b,
                 const float* __restrict__ c2w, const float* __restrict__ c2b) {
    extern __shared__ float sm[];
    float*    s_in   = sm + OFF_IN;
    float*    s_c1w  = sm + OFF_C1W;
    float*    s_c1b  = sm + OFF_C1B;
    float*    s_c2b  = sm + OFF_C2B;
    int*      s_coff = (int*)(sm + OFF_COFF);
    float*    s_c1   = sm + OFF_C1;
    unsigned* s_c1p  = (unsigned*)(sm + OFF_C1);
    uint2*    s_Bf   = (uint2*)(sm + OFF_BF);

    const int b = blockIdx.x;
    const int t = threadIdx.x;

    const float* xin = x + b * 784;
    for (int i = t; i < 784; i += CONV_THREADS) s_in[i] = xin[i];
    for (int i = t; i < 288; i += CONV_THREADS) s_c1w[i] = c1w[i];
    if (t < 32) s_c1b[t] = c1b[t];
    if (t >= 64 && t < 128) s_c2b[t - 64] = c2b[t - 64];
    if (t >= 128 && t < 416) {
        int k = t - 128;
        int ic = k / 9, kk = k - ic * 9;
        s_coff[k] = ic * 676 + (kk / 3) * 26 + (kk % 3);
    }
    for (int i = t; i < 18432; i += CONV_THREADS) s_c1[i] = c2w[i];
    __syncthreads();

    for (int i = t; i < 8 * NKS * 32; i += CONV_THREADS) {
        int lane = i & 31;
        int rest = i >> 5;
        int ks = rest % NKS;
        int nt = rest / NKS;
        int tg = lane & 3, g = lane >> 2;
        int n = nt * 8 + g;
        int k0 = ks * 16 + 2 * tg;
        const float* wr = s_c1 + n * 288;
        float w0 = wr[k0],     w1 = wr[k0 + 1];
        float w8 = wr[k0 + 8], w9 = wr[k0 + 9];
        __half2 h0 = __floats2half2_rn(w0, w1);
        __half2 h1 = __floats2half2_rn(w8, w9);
        float2 r0 = __half22float2(h0);
        float2 r1 = __half22float2(h1);
        __half2 l0 = __floats2half2_rn((w0 - r0.x) * 64.f, (w1 - r0.y) * 64.f);
        __half2 l1 = __floats2half2_rn((w8 - r1.x) * 64.f, (w9 - r1.y) * 64.f);
        __half2 s0 = __floats2half2_rn(w0 * 0.015625f, w1 * 0.015625f);
        __half2 s1 = __floats2half2_rn(w8 * 0.015625f, w9 * 0.015625f);
        int slot = (nt * NKS + ks) * 32 + lane;
        s_Bf[slot]                 = make_uint2(h2u(h0), h2u(h1));
        s_Bf[slot + 8 * NKS * 32]  = make_uint2(h2u(s0), h2u(s1));
        s_Bf[slot + 16 * NKS * 32] = make_uint2(h2u(l0), h2u(l1));
    }
    __syncthreads();

    for (int i = t; i < 21632; i += CONV_THREADS) {
        int c  = i / 676;
        int p  = i - c * 676;
        int y  = p / 26;
        int xx = p - y * 26;
        const float* wv = s_c1w + c * 9;
        const float* ip = s_in + y * 28 + xx;
        float acc = s_c1b[c];
        #pragma unroll
        for (int ky = 0; ky < 3; ky++)
            #pragma unroll
            for (int kx = 0; kx < 3; kx++)
                acc = fmaf(ip[ky * 28 + kx], wv[ky * 3 + kx], acc);
        s_c1p[i] = packh(fmaxf(acc, 0.f));
    }
    __syncthreads();

    const int lane = t & 31;
    const int wid  = t >> 5;
    const int g    = lane >> 2;
    const int tg   = lane & 3;
    unsigned* hbp = g_hp + (size_t)b * D_DIM;
    const __half2 k5 = __floats2half2_rn(0.03125f, 0.03125f);
    const __half2 k6 = __floats2half2_rn(0.015625f, 0.015625f);

    #pragma unroll
    for (int ti = 0; ti < 2; ti++) {
        const int tt = wid * 2 + ti;
        const int q  = tt * 4 + (g & 3);
        const int p  = (q / 12) * 52 + (q % 12) * 2 + (g >> 2);
        const int p26 = p + 26;

        float acc[8][4];
        #pragma unroll
        for (int nt = 0; nt < 8; nt++)
            #pragma unroll
            for (int i = 0; i < 4; i++) acc[nt][i] = 0.f;

        for (int ks = 0; ks < NKS; ks++) {
            const int kb = ks * 16 + 2 * tg;
            const int c0 = s_coff[kb],     c1 = s_coff[kb + 1];
            const int c2 = s_coff[kb + 8], c3 = s_coff[kb + 9];
            unsigned u00 = s_c1p[p + c0],   u01 = s_c1p[p + c1];
            unsigned u02 = s_c1p[p + c2],   u03 = s_c1p[p + c3];
            unsigned u10 = s_c1p[p26 + c0], u11 = s_c1p[p26 + c1];
            unsigned u12 = s_c1p[p26 + c2], u13 = s_c1p[p26 + c3];

            unsigned ah0 = __byte_perm(u00, u01, 0x5410);
            unsigned ah1 = __byte_perm(u10, u11, 0x5410);
            unsigned ah2 = __byte_perm(u02, u03, 0x5410);
            unsigned ah3 = __byte_perm(u12, u13, 0x5410);
            unsigned al0 = h2u(__hmul2(u2h(__byte_perm(u00, u01, 0x7632)), k5));
            unsigned al1 = h2u(__hmul2(u2h(__byte_perm(u10, u11, 0x7632)), k5));
            unsigned al2 = h2u(__hmul2(u2h(__byte_perm(u02, u03, 0x7632)), k5));
            unsigned al3 = h2u(__hmul2(u2h(__byte_perm(u12, u13, 0x7632)), k5));
            unsigned us0 = h2u(__hmul2(u2h(ah0), k6));
            unsigned us1 = h2u(__hmul2(u2h(ah1), k6));
            unsigned us2 = h2u(__hmul2(u2h(ah2), k6));
            unsigned us3 = h2u(__hmul2(u2h(ah3), k6));

            const uint2* bp = s_Bf + ks * 32 + lane;
            #pragma unroll
            for (int nt = 0; nt < 8; nt++) {
                uint2 bwh = bp[nt * (NKS * 32)];
                uint2 bws = bp[nt * (NKS * 32) + 8 * NKS * 32];
                uint2 bwl = bp[nt * (NKS * 32) + 16 * NKS * 32];
                mma_f16(acc[nt], ah0, ah1, ah2, ah3, bwh.x, bwh.y);
                mma_f16(acc[nt], al0, al1, al2, al3, bws.x, bws.y);
                mma_f16(acc[nt], us0, us1, us2, us3, bwl.x, bwl.y);
            }
        }

        #pragma unroll
        for (int nt = 0; nt < 8; nt++) {
            float v0 = fmaxf(acc[nt][0], acc[nt][2]);
            float v1 = fmaxf(acc[nt][1], acc[nt][3]);
            v0 = fmaxf(v0, __shfl_xor_sync(0xFFFFFFFFu, v0, 16));
            v1 = fmaxf(v1, __shfl_xor_sync(0xFFFFFFFFu, v1, 16));
            int ch0 = nt * 8 + 2 * tg;
            if ((lane < 16) == (nt < 4)) {
                hbp[ch0 * 144 + q]       = packh(fmaxf(v0 + s_c2b[ch0], 0.f));
                hbp[(ch0 + 1) * 144 + q] = packh(fmaxf(v1 + s_c2b[ch0 + 1], 0.f));
            }
        }
    }
}

// ---------------- top-1 gate: 8 tokens/block, warp-shuffle reduction ---------
__global__ __launch_bounds__(256)
void gate_kernel(const float* __restrict__ gate_w) {
    __shared__ float red[GTOK * 8][9];        // [j=tok*8+e][warp]
    const int bb = blockIdx.x * GTOK;
    const int t  = threadIdx.x;
    const int w  = t >> 5, l = t & 31;

    float acc[GTOK][8];
    #pragma unroll
    for (int tk = 0; tk < GTOK; tk++)
        #pragma unroll
        for (int e = 0; e < 8; e++) acc[tk][e] = 0.f;

    for (int it = 0; it < 36; it++) {
        int d = it * 256 + t;
        const float4* gp = (const float4*)(gate_w + (size_t)d * 8);
        float4 ga = gp[0], gb = gp[1];
        #pragma unroll
        for (int tk = 0; tk < GTOK; tk++) {
            float hv = unpackh(g_hp[(size_t)(bb + tk) * D_DIM + d]);
            acc[tk][0] = fmaf(hv, ga.x, acc[tk][0]);
            acc[tk][1] = fmaf(hv, ga.y, acc[tk][1]);
            acc[tk][2] = fmaf(hv, ga.z, acc[tk][2]);
            acc[tk][3] = fmaf(hv, ga.w, acc[tk][3]);
            acc[tk][4] = fmaf(hv, gb.x, acc[tk][4]);
            acc[tk][5] = fmaf(hv, gb.y, acc[tk][5]);
            acc[tk][6] = fmaf(hv, gb.z, acc[tk][6]);
            acc[tk][7] = fmaf(hv, gb.w, acc[tk][7]);
        }
    }

    #pragma unroll
    for (int tk = 0; tk < GTOK; tk++)
        #pragma unroll
        for (int e = 0; e < 8; e++) {
            float v = acc[tk][e];
            #pragma unroll
            for (int off = 16; off > 0; off >>= 1)
                v += __shfl_down_sync(0xFFFFFFFFu, v, off);
            if (l == 0) red[tk * 8 + e][w] = v;
        }
    __syncthreads();

    if (t < GTOK) {
        float lg[8];
        #pragma unroll
        for (int e = 0; e < 8; e++) {
            float s = 0.f;
            #pragma unroll
            for (int ww = 0; ww < 8; ww++) s += red[t * 8 + e][ww];
            lg[e] = s;
        }
        float m = lg[0];
        int idx = 0;
        #pragma unroll
        for (int e = 1; e < 8; e++) if (lg[e] > m) { m = lg[e]; idx = e; }
        float s = 0.f;
        #pragma unroll
        for (int e = 0; e < 8; e++) s += expf(lg[e] - m);
        int tok = bb + t;
        g_scale[tok] = 1.f / s;
        int pos = atomicAdd(&g_cnt[idx], 1);
        g_bucket[idx * B_TOK + pos] = tok;
    }
}

// ---------------- ffn stage 1: fp16 2-term tensor GEMM, M=64 -----------------
// grid (64 mt, 8 e, 6 sp), 256 thr. Conflict-free strides: A 68, B 136.
#define AST 68
#define BST 136
__global__ __launch_bounds__(256)
void ffn1_kernel() {
    __shared__ unsigned A_s[64 * AST];   // [k][tok]
    __shared__ unsigned B_s[32 * BST];   // [kpair][n]
    __shared__ int tok_s[64];

    const int e = blockIdx.y, mt = blockIdx.x, sp = blockIdx.z, t = threadIdx.x;
    const int count = g_cnt[e];
    if (mt * 64 >= count) return;
    if (t < 64) {
        int r = mt * 64 + t;
        tok_s[t] = (r < count) ? g_bucket[e * B_TOK + r] : -1;
    }
    __syncthreads();

    const int lane = t & 31, w = t >> 5;
    const int g = lane >> 2, tg = lane & 3;
    const int mt2 = w & 3;                 // m16 tile (0..3)
    const int nh  = w >> 2;                // n half (0..1), 64 cols each
    const int tokA = mt2 * 16 + g;
    const __half2 k11 = __floats2half2_rn(4.8828125e-4f, 4.8828125e-4f);

    float acc[8][4];
    #pragma unroll
    for (int nt = 0; nt < 8; nt++)
        #pragma unroll
        for (int i = 0; i < 4; i++) acc[nt][i] = 0.f;

    const int rowbase = e * 4608 + sp * 768;

    for (int kb = 0; kb < KCH; kb += 64) {
        unsigned uA[16];
        uint4 uB[4];
        #pragma unroll
        for (int v = 0; v < 16; v++) {
            int i = t + 256 * v;
            int ltok = i >> 6, lk = i & 63;
            int tk = tok_s[ltok];
            uA[v] = g_hp[(size_t)(tk >= 0 ? tk : 0) * D_DIM + sp * KCH + kb + lk];
        }
        #pragma unroll
        for (int v = 0; v < 4; v++) {
            int f = t + 256 * v;
            int kp = f >> 5, n4 = (f & 31) * 4;
            uB[v] = *(const uint4*)&g_w1h[(size_t)(rowbase + (kb >> 1) + kp) * 128 + n4];
        }
        __syncthreads();
        #pragma unroll
        for (int v = 0; v < 16; v++) {
            int i = t + 256 * v;
            A_s[(i & 63) * AST + (i >> 6)] = uA[v];
        }
        #pragma unroll
        for (int v = 0; v < 4; v++) {
            int f = t + 256 * v;
            int kp = f >> 5, n4 = (f & 31) * 4;
            *(uint4*)&B_s[kp * BST + n4] = uB[v];
        }
        __syncthreads();

        #pragma unroll
        for (int s = 0; s < 4; s++) {
            const int K = s * 16;
            unsigned u00 = A_s[(K + 2 * tg) * AST + tokA];
            unsigned u01 = A_s[(K + 2 * tg + 1) * AST + tokA];
            unsigned u02 = A_s[(K + 2 * tg + 8) * AST + tokA];
            unsigned u03 = A_s[(K + 2 * tg + 9) * AST + tokA];
            unsigned u10 = A_s[(K + 2 * tg) * AST + tokA + 8];
            unsigned u11 = A_s[(K + 2 * tg + 1) * AST + tokA + 8];
            unsigned u12 = A_s[(K + 2 * tg + 8) * AST + tokA + 8];
            unsigned u13 = A_s[(K + 2 * tg + 9) * AST + tokA + 8];
            unsigned ah0 = __byte_perm(u00, u01, 0x5410);
            unsigned ah1 = __byte_perm(u10, u11, 0x5410);
            unsigned ah2 = __byte_perm(u02, u03, 0x5410);
            unsigned ah3 = __byte_perm(u12, u13, 0x5410);
            unsigned al0 = h2u(__hmul2(u2h(__byte_perm(u00, u01, 0x7632)), k11));
            unsigned al1 = h2u(__hmul2(u2h(__byte_perm(u10, u11, 0x7632)), k11));
            unsigned al2 = h2u(__hmul2(u2h(__byte_perm(u02, u03, 0x7632)), k11));
            unsigned al3 = h2u(__hmul2(u2h(__byte_perm(u12, u13, 0x7632)), k11));
            const int kq = s * 8;
            #pragma unroll
            for (int nt = 0; nt < 8; nt++) {
                int n = nh * 64 + nt * 8 + g;
                unsigned b0 = B_s[(kq + tg) * BST + n];
                unsigned b1 = B_s[(kq + tg + 4) * BST + n];
                mma_f16(acc[nt], ah0, ah1, ah2, ah3, b0, b1);
                mma_f16(acc[nt], al0, al1, al2, al3, b0, b1);
            }
        }
        __syncthreads();
    }

    int tk0 = tok_s[tokA];
    int tk1 = tok_s[tokA + 8];
    #pragma unroll
    for (int nt = 0; nt < 8; nt++) {
        int n = nh * 64 + nt * 8 + 2 * tg;
        if (tk0 >= 0) {
            g_part[sp][tk0][n]     = acc[nt][0];
            g_part[sp][tk0][n + 1] = acc[nt][1];
        }
        if (tk1 >= 0) {
            g_part[sp][tk1][n]     = acc[nt][2];
            g_part[sp][tk1][n + 1] = acc[nt][3];
        }
    }
}

// ---------------- ffn stage 2: reduce + b1 + relu + w2 + log_softmax --------
__global__ __launch_bounds__(256)
void ffn2_kernel(const float* __restrict__ b1, const float* __restrict__ w2,
                 const float* __restrict__ b2, float* __restrict__ out) {
    __shared__ float he_s[32 * 129];
    __shared__ int tok_s[32];
    const int e = blockIdx.y, mt = blockIdx.x, t = threadIdx.x;
    const int count = g_cnt[e];
    if (mt * 32 >= count) return;
    if (t < 32) {
        int r = mt * 32 + t;
        tok_s[t] = (r < count) ? g_bucket[e * B_TOK + r] : -1;
    }
    __syncthreads();
    const float* b1e = b1 + e * H_DIM;
    for (int i4 = t; i4 < 1024; i4 += 256) {
        int row = i4 >> 5, c4 = (i4 & 31) << 2;
        int tok = tok_s[row];
        float sx = 0.f, sy = 0.f, sz = 0.f, sw = 0.f;
        if (tok >= 0)
            #pragma unroll
            for (int sp = 0; sp < SPLITS; sp++) {
                float4 p = *(const float4*)&g_part[sp][tok][c4];
                sx += p.x; sy += p.y; sz += p.z; sw += p.w;
            }
        he_s[row * 129 + c4 + 0] = fmaxf(sx + b1e[c4 + 0], 0.f);
        he_s[row * 129 + c4 + 1] = fmaxf(sy + b1e[c4 + 1], 0.f);
        he_s[row * 129 + c4 + 2] = fmaxf(sz + b1e[c4 + 2], 0.f);
        he_s[row * 129 + c4 + 3] = fmaxf(sw + b1e[c4 + 3], 0.f);
    }
    __syncthreads();
    if (t < 32) {
        int r = mt * 32 + t;
        if (r < count) {
            int tok = tok_s[t];
            const float* w2e = w2 + e * (H_DIM * O_DIM);
            const float* b2e = b2 + e * O_DIM;
            float o[O_DIM];
            #pragma unroll
            for (int oo = 0; oo < O_DIM; oo++) o[oo] = b2e[oo];
            const float* hh = he_s + t * 129;
            for (int hi = 0; hi < H_DIM; hi++) {
                float hv = hh[hi];
                const float* wr = w2e + hi * O_DIM;
                #pragma unroll
                for (int oo = 0; oo < O_DIM; oo++)
                    o[oo] = fmaf(hv, wr[oo], o[oo]);
            }
            float sc = g_scale[tok];
            float m = -1e30f;
            #pragma unroll
            for (int oo = 0; oo < O_DIM; oo++) { o[oo] *= sc; m = fmaxf(m, o[oo]); }
            float s = 0.f;
            #pragma unroll
            for (int oo = 0; oo < O_DIM; oo++) s += expf(o[oo] - m);
            float lse = m + logf(s);
            #pragma unroll
            for (int oo = 0; oo < O_DIM; oo++)
                out[tok * O_DIM + oo] = o[oo] - lse;
        }
    }
}

// ---------------- launch -----------------------------------------------------
extern "C" void kernel_launch(void* const* d_in, const int* in_sizes, int n_in,
                              void* d_out, int out_size) {
    const float* x   = (const float*)d_in[0];
    const float* c1w = (const float*)d_in[1];
    const float* c1b = (const float*)d_in[2];
    const float* c2w = (const float*)d_in[3];
    const float* c2b = (const float*)d_in[4];
    const float* gw  = (const float*)d_in[5];
    const float* w1  = (const float*)d_in[6];
    const float* b1  = (const float*)d_in[7];
    const float* w2  = (const float*)d_in[8];
    const float* b2  = (const float*)d_in[9];
    float* out = (float*)d_out;

    cudaFuncSetAttribute(conv_kernel, cudaFuncAttributeMaxDynamicSharedMemorySize,
                         CONV_SMEM_FLOATS * (int)sizeof(float));
    reset_kernel<<<1, 32>>>();
    w1pack_kernel<<<18432, 256>>>(w1);
    conv_kernel<<<B_TOK, CONV_THREADS, CONV_SMEM_FLOATS * sizeof(float)>>>(
        x, c1w, c1b, c2w, c2b);
    gate_kernel<<<B_TOK / GTOK, 256>>>(gw);
    ffn1_kernel<<<dim3(64, E_EXP, SPLITS), 256>>>();
    ffn2_kernel<<<dim3(128, E_EXP), 256>>>(b1, w2, b2, out);
}